// round 9
// baseline (speedup 1.0000x reference)
#include <cuda_runtime.h>
#include <cuda_fp16.h>
#include <stdint.h>
#include <math.h>

#define N_FRAMES 2048
#define N_AGENTS 32
#define N_ROWS 65536
#define FEAT 512
#define HID 140
#define OUT2 256

#define OFF_A0 (N_ROWS * OUT2)
#define OFF_A1 (OFF_A0 + N_ROWS * 8)
#define OFF_A2 (OFF_A1 + N_ROWS * 6)

// fragment tables: per-lane B fragments exactly as ldmatrix would produce them.
// g_w1f: W1aug [144n x 576k]  -> kt in [0,36), nt in [0,18)
// g_wif: Wiaug [24n x 1024k]  -> kt in [0,64), nt in [0,3)
// g_w2f: W2aug [256n x 144k]  -> kt in [0,9),  nt in [0,32)
__device__ __align__(16) uint2 g_w1f[36 * 18 * 32];   // 165.9 KB
__device__ __align__(16) uint2 g_wif[64 * 3 * 32];    // 49.2 KB
__device__ __align__(16) uint2 g_w2f[9 * 32 * 32];    // 73.7 KB

// ---------------------------------------------------------------- helpers
__device__ __forceinline__ uint32_t smaddr(const void* p) {
    return (uint32_t)__cvta_generic_to_shared(p);
}
__device__ __forceinline__ void ldsm_x4(uint32_t* r, uint32_t a) {
    asm volatile("ldmatrix.sync.aligned.m8n8.x4.shared.b16 {%0,%1,%2,%3}, [%4];"
        : "=r"(r[0]), "=r"(r[1]), "=r"(r[2]), "=r"(r[3]) : "r"(a));
}
__device__ __forceinline__ void mma_f16(float* d, const uint32_t* a, const uint32_t* b) {
    asm volatile("mma.sync.aligned.m16n8k16.row.col.f32.f16.f16.f32 "
        "{%0,%1,%2,%3}, {%4,%5,%6,%7}, {%8,%9}, {%0,%1,%2,%3};"
        : "+f"(d[0]), "+f"(d[1]), "+f"(d[2]), "+f"(d[3])
        : "r"(a[0]), "r"(a[1]), "r"(a[2]), "r"(a[3]), "r"(b[0]), "r"(b[1]));
}
__device__ __forceinline__ uint32_t pack2h(__half a, __half b) {
    __half2 t; t.x = a; t.y = b;
    return *reinterpret_cast<uint32_t*>(&t);
}
__device__ __forceinline__ uint32_t pack2f(float a, float b) {
    return pack2h(__float2half_rn(a), __float2half_rn(b));
}

// ---------------------------------------------------------------- prep
__device__ __forceinline__ float w1aug(int n, int k,
    const float* __restrict__ W1, const float* __restrict__ b1)
{
    if (n >= HID) return 0.f;
    if (k < 530)  return W1[(size_t)k * HID + n];
    if (k == 530) return b1[n];
    return 0.f;
}
__device__ __forceinline__ float wiaug(int n, int k,
    const float* __restrict__ Wi0, const float* __restrict__ Wi1,
    const float* __restrict__ Wi2)
{
    if (n < 8)  return Wi0[(size_t)k * 8 + n];
    if (n < 14) return Wi1[(size_t)k * 6 + (n - 8)];
    if (n < 18) return Wi2[(size_t)k * 4 + (n - 14)];
    return 0.f;
}
__device__ __forceinline__ float w2aug(int n, int k,
    const float* __restrict__ W2, const float* __restrict__ b2)
{
    if (k < HID)  return W2[(size_t)k * OUT2 + n];
    if (k == HID) return b2[n];
    return 0.f;
}

__global__ void prep_kernel(
    const float* __restrict__ W1, const float* __restrict__ b1,
    const float* __restrict__ W2, const float* __restrict__ b2,
    const float* __restrict__ Wi0, const float* __restrict__ Wi1,
    const float* __restrict__ Wi2)
{
    int idx = blockIdx.x * 256 + threadIdx.x;
    int lane = idx & 31, t = idx >> 5;
    if (idx < 36 * 18 * 32) {           // W1 fragments
        int kt = t / 18, nt = t - kt * 18;
        int n = nt * 8 + (lane >> 2);
        int k = kt * 16 + 2 * (lane & 3);
        uint2 u;
        u.x = pack2f(w1aug(n, k, W1, b1),     w1aug(n, k + 1, W1, b1));
        u.y = pack2f(w1aug(n, k + 8, W1, b1), w1aug(n, k + 9, W1, b1));
        g_w1f[idx] = u;
    }
    if (idx < 64 * 3 * 32) {            // Wi fragments
        int kt = t / 3, nt = t - kt * 3;
        int n = nt * 8 + (lane >> 2);
        int k = kt * 16 + 2 * (lane & 3);
        uint2 u;
        u.x = pack2f(wiaug(n, k, Wi0, Wi1, Wi2),     wiaug(n, k + 1, Wi0, Wi1, Wi2));
        u.y = pack2f(wiaug(n, k + 8, Wi0, Wi1, Wi2), wiaug(n, k + 9, Wi0, Wi1, Wi2));
        g_wif[idx] = u;
    }
    if (idx < 9 * 32 * 32) {            // W2 fragments
        int kt = t / 32, nt = t - kt * 32;
        int n = nt * 8 + (lane >> 2);
        int k = kt * 16 + 2 * (lane & 3);
        uint2 u;
        u.x = pack2f(w2aug(n, k, W2, b2),     w2aug(n, k + 1, W2, b2));
        u.y = pack2f(w2aug(n, k + 8, W2, b2), w2aug(n, k + 9, W2, b2));
        g_w2f[idx] = u;
    }
}

// stage 128x64 fp32 feature chunk -> fp16 smem (stride 72 halfs)
__device__ __forceinline__ void stage_feat(
    __half* sA, const float* __restrict__ src, int row0, int c0, int tid)
{
    #pragma unroll
    for (int j = 0; j < 8; j++) {
        int i = tid + j * 256;
        int r = i >> 4, ce = (i & 15) << 2;
        float4 v = *(const float4*)(src + (size_t)(row0 + r) * FEAT + c0 + ce);
        uint2 u;
        u.x = pack2f(v.x, v.y);
        u.y = pack2f(v.z, v.w);
        *(uint2*)(sA + r * 72 + ce) = u;
    }
}
// special chunk (one-hot + bias-one): thread r owns row r -> race-free
__device__ __forceinline__ void stage_special(
    __half* sA, const int* __restrict__ actions, int row0, int tid)
{
    if (tid < 128) {
        int r = tid;
        #pragma unroll
        for (int q = 0; q < 8; q++)
            *(uint4*)(sA + r * 72 + q * 8) = make_uint4(0, 0, 0, 0);
        int f = (row0 + r) >> 5, ag = (row0 + r) & 31;
        int i0 = actions[(f * 3 + 0) * N_AGENTS + ag];
        int i1 = actions[(f * 3 + 1) * N_AGENTS + ag];
        int i2 = actions[(f * 3 + 2) * N_AGENTS + ag];
        __half one = __float2half_rn(1.f);
        sA[r * 72 + i0] = one;
        sA[r * 72 + 8 + i1] = one;
        sA[r * 72 + 14 + i2] = one;
        sA[r * 72 + 18] = one;             // b1 column (k=530)
    }
}

// ---------------------------------------------------------------- FUSED ALL v4
// B operands come straight from fragment tables via LDG.64 (no smem staging).
// Only A stages through smem (fp32->fp16 conversion), double-buffered.
// smem: A0 @0 (18432) | A1 @18432 (18432) | sL @40960 (12800)  total 53760
// phase2/3: sHid aliases @0 (128*152*2 = 38912)
#define SA0  0
#define SA1  18432
#define SL   40960
#define SM_TOTAL 53760

__global__ __launch_bounds__(256, 2) void fused_all(
    const float* __restrict__ cur, const float* __restrict__ nxt,
    const int* __restrict__ actions, float* __restrict__ out)
{
    extern __shared__ char smem[];
    float* sL = (float*)(smem + SL);

    const int tid = threadIdx.x, lane = tid & 31, w = tid >> 5;
    const int row0 = blockIdx.x * 128;
    const int m0 = (w >> 1) * 32;               // gemm1 warp rows
    const int wodd = w & 1;                     // gemm1 n-half selector
    const int ntB = wodd * 9;                   // base n-tile in W1f
    const int mI = w * 16;                      // inv rows (== m0 + wodd*16)

    // ================= phase 1 =================
    float acc1[2][9][4];
    #pragma unroll
    for (int a = 0; a < 2; a++)
        #pragma unroll
        for (int b = 0; b < 9; b++)
            #pragma unroll
            for (int c = 0; c < 4; c++) acc1[a][b][c] = 0.f;
    float accI[3][4];
    #pragma unroll
    for (int b = 0; b < 3; b++)
        #pragma unroll
        for (int c = 0; c < 4; c++) accI[b][c] = 0.f;

    // prologue: stage chunk 0
    stage_feat((__half*)(smem + SA0), cur, row0, 0, tid);
    __syncthreads();

    for (int kb = 0; kb < 17; kb++) {
        __half* cA = (__half*)(smem + ((kb & 1) ? SA1 : SA0));
        const int nb = kb + 1;
        __half* nA = (__half*)(smem + ((nb & 1) ? SA1 : SA0));

        // ---- stage next A chunk (other buffer; overlaps compute)
        if (nb < 8)        stage_feat(nA, cur, row0, nb * 64, tid);
        else if (nb < 16)  stage_feat(nA, nxt, row0, (nb - 8) * 64, tid);
        else if (nb == 16) stage_special(nA, actions, row0, tid);

        // ---- compute current chunk
        const bool g1 = (kb < 8) || (kb == 16);
        const bool iv = (kb < 16);
        const int kmax = (kb == 16) ? 2 : 4;
        for (int ks = 0; ks < kmax; ks++) {
            int k0 = ks * 16;
            uint32_t a[2][4];
            if (g1) {
                #pragma unroll
                for (int mt = 0; mt < 2; mt++) {
                    int r = m0 + mt * 16 + (lane & 15);
                    int c = k0 + ((lane >> 4) << 3);
                    ldsm_x4(a[mt], smaddr(cA + r * 72 + c));
                }
            } else {
                int r = mI + (lane & 15);
                int c = k0 + ((lane >> 4) << 3);
                ldsm_x4(a[wodd], smaddr(cA + r * 72 + c));
            }
            if (g1) {
                int kt = (kb == 16) ? 32 + ks : kb * 4 + ks;
                const uint2* bp = g_w1f + (size_t)(kt * 18 + ntB) * 32 + lane;
                #pragma unroll
                for (int nt = 0; nt < 9; nt++) {
                    uint2 bb = bp[nt * 32];
                    mma_f16(acc1[0][nt], a[0], (const uint32_t*)&bb);
                    mma_f16(acc1[1][nt], a[1], (const uint32_t*)&bb);
                }
            }
            if (iv) {
                int kt = kb * 4 + ks;
                const uint2* wp = g_wif + (size_t)(kt * 3) * 32 + lane;
                const uint32_t* ai = a[wodd];
                #pragma unroll
                for (int nt = 0; nt < 3; nt++) {
                    uint2 bb = wp[nt * 32];
                    mma_f16(accI[nt], ai, (const uint32_t*)&bb);
                }
            }
        }
        __syncthreads();
    }

    // ================= phase 2: hid -> smem, logits -> smem, softmax =========
    __half* sHid = (__half*)(smem);         // aliases dead A buffers
    const int n0 = wodd * 72;
    #pragma unroll
    for (int mt = 0; mt < 2; mt++) {
        #pragma unroll
        for (int nt = 0; nt < 9; nt++) {
            int col = n0 + nt * 8 + ((lane & 3) << 1);
            int rl = m0 + mt * 16 + (lane >> 2);
            #pragma unroll
            for (int h = 0; h < 2; h++) {
                float v0 = acc1[mt][nt][h * 2 + 0];
                float v1 = acc1[mt][nt][h * 2 + 1];
                if (col == 140) v0 = 1.f;       // ones column (b2)
                *(uint32_t*)(sHid + (rl + h * 8) * 152 + col) = pack2f(v0, v1);
            }
        }
    }
    #pragma unroll
    for (int nt = 0; nt < 3; nt++) {
        int col = nt * 8 + ((lane & 3) << 1);
        int rl = mI + (lane >> 2);
        sL[rl * 25 + col]           = accI[nt][0];
        sL[rl * 25 + col + 1]       = accI[nt][1];
        sL[(rl + 8) * 25 + col]     = accI[nt][2];
        sL[(rl + 8) * 25 + col + 1] = accI[nt][3];
    }
    __syncthreads();

    // softmax over 32 agents, per frame (4 frames), per logit column
    if (tid < 72) {
        int f = tid / 18, j = tid - f * 18;
        float vals[32], mx = -1e30f;
        #pragma unroll
        for (int a = 0; a < 32; a++) {
            vals[a] = sL[(f * 32 + a) * 25 + j];
            mx = fmaxf(mx, vals[a]);
        }
        float s = 0.f;
        #pragma unroll
        for (int a = 0; a < 32; a++) { vals[a] = expf(vals[a] - mx); s += vals[a]; }
        float inv = 1.f / s;
        int frame = blockIdx.x * 4 + f;
        if (j < 8) {
            size_t base = OFF_A0 + (size_t)(frame * 32) * 8 + j;
            #pragma unroll
            for (int a = 0; a < 32; a++) out[base + (size_t)a * 8] = vals[a] * inv;
        } else if (j < 14) {
            size_t base = OFF_A1 + (size_t)(frame * 32) * 6 + (j - 8);
            #pragma unroll
            for (int a = 0; a < 32; a++) out[base + (size_t)a * 6] = vals[a] * inv;
        } else {
            size_t base = OFF_A2 + (size_t)(frame * 32) * 4 + (j - 14);
            #pragma unroll
            for (int a = 0; a < 32; a++) out[base + (size_t)a * 4] = vals[a] * inv;
        }
    }
    __syncthreads();

    // ================= phase 3: gemm2 (W2 fragments direct from global) ======
    // warp tile 32 rows x 32 cols per 64-col chunk; no syncs needed.
    const int m2 = (w >> 1) * 32;
    const int n2g = wodd * 4;                   // n-tile group offset (in 8-col tiles)
    for (int c = 0; c < 4; c++) {
        float acc[2][4][4];
        #pragma unroll
        for (int a = 0; a < 2; a++)
            #pragma unroll
            for (int b = 0; b < 4; b++)
                #pragma unroll
                for (int q = 0; q < 4; q++) acc[a][b][q] = 0.f;

        #pragma unroll
        for (int ks = 0; ks < 9; ks++) {
            int k0 = ks * 16;
            uint32_t a[2][4];
            #pragma unroll
            for (int mt = 0; mt < 2; mt++) {
                int r = m2 + mt * 16 + (lane & 15);
                int kc = k0 + ((lane >> 4) << 3);
                ldsm_x4(a[mt], smaddr(sHid + r * 152 + kc));
            }
            const uint2* bp = g_w2f + (size_t)(ks * 32 + c * 8 + n2g) * 32 + lane;
            #pragma unroll
            for (int nt = 0; nt < 4; nt++) {
                uint2 bb = bp[nt * 32];
                mma_f16(acc[0][nt], a[0], (const uint32_t*)&bb);
                mma_f16(acc[1][nt], a[1], (const uint32_t*)&bb);
            }
        }

        #pragma unroll
        for (int mt = 0; mt < 2; mt++) {
            #pragma unroll
            for (int nt = 0; nt < 4; nt++) {
                int col = c * 64 + wodd * 32 + nt * 8 + ((lane & 3) << 1);
                int rb = row0 + m2 + mt * 16 + (lane >> 2);
                *(float2*)(out + (size_t)rb * OUT2 + col) =
                    make_float2(acc[mt][nt][0], acc[mt][nt][1]);
                *(float2*)(out + (size_t)(rb + 8) * OUT2 + col) =
                    make_float2(acc[mt][nt][2], acc[mt][nt][3]);
            }
        }
    }
}

// ----------------------------------------------------------------
extern "C" void kernel_launch(void* const* d_in, const int* in_sizes, int n_in,
                              void* d_out, int out_size)
{
    const float* cur  = (const float*)d_in[0];
    const float* nxt  = (const float*)d_in[1];
    const int*   acts = (const int*)  d_in[2];
    const float* W1   = (const float*)d_in[3];
    const float* b1   = (const float*)d_in[4];
    const float* W2   = (const float*)d_in[5];
    const float* b2   = (const float*)d_in[6];
    const float* Wi0  = (const float*)d_in[7];
    const float* Wi1  = (const float*)d_in[9];
    const float* Wi2  = (const float*)d_in[11];
    float* out = (float*)d_out;

    cudaFuncSetAttribute(fused_all, cudaFuncAttributeMaxDynamicSharedMemorySize, SM_TOTAL);

    prep_kernel<<<81, 256>>>(W1, b1, W2, b2, Wi0, Wi1, Wi2);
    fused_all<<<N_ROWS / 128, 256, SM_TOTAL>>>(cur, nxt, acts, out);
}

// round 10
// speedup vs baseline: 1.1709x; 1.1709x over previous
#include <cuda_runtime.h>
#include <cuda_fp16.h>
#include <stdint.h>
#include <math.h>

#define N_FRAMES 2048
#define N_AGENTS 32
#define N_ROWS 65536
#define FEAT 512
#define HID 140
#define OUT2 256

#define OFF_A0 (N_ROWS * OUT2)
#define OFF_A1 (OFF_A0 + N_ROWS * 8)
#define OFF_A2 (OFF_A1 + N_ROWS * 6)

// padded dims
#define K1P 576   // 512 feat + 18 onehot + bias@530 + pad
#define N1P 144   // 140 hid + ones@140 + pad
#define K2P 144
#define KIP 1024  // cur|next
#define NIP 24

// single-fp16 transposed weights
__device__ __align__(16) __half g_w1t[N1P * K1P];     // [n][k]
__device__ __align__(16) __half g_wit[NIP * KIP];     // [n][k]
__device__ __align__(16) __half g_w2t[OUT2 * K2P];    // [n][k]

// ---------------------------------------------------------------- helpers
__device__ __forceinline__ uint32_t smaddr(const void* p) {
    return (uint32_t)__cvta_generic_to_shared(p);
}
__device__ __forceinline__ void ldsm_x4(uint32_t* r, uint32_t a) {
    asm volatile("ldmatrix.sync.aligned.m8n8.x4.shared.b16 {%0,%1,%2,%3}, [%4];"
        : "=r"(r[0]), "=r"(r[1]), "=r"(r[2]), "=r"(r[3]) : "r"(a));
}
__device__ __forceinline__ void ldsm_x2(uint32_t* r, uint32_t a) {
    asm volatile("ldmatrix.sync.aligned.m8n8.x2.shared.b16 {%0,%1}, [%2];"
        : "=r"(r[0]), "=r"(r[1]) : "r"(a));
}
__device__ __forceinline__ void mma_f16(float* d, const uint32_t* a, const uint32_t* b) {
    asm volatile("mma.sync.aligned.m16n8k16.row.col.f32.f16.f16.f32 "
        "{%0,%1,%2,%3}, {%4,%5,%6,%7}, {%8,%9}, {%0,%1,%2,%3};"
        : "+f"(d[0]), "+f"(d[1]), "+f"(d[2]), "+f"(d[3])
        : "r"(a[0]), "r"(a[1]), "r"(a[2]), "r"(a[3]), "r"(b[0]), "r"(b[1]));
}
__device__ __forceinline__ uint32_t pack2h(__half a, __half b) {
    __half2 t; t.x = a; t.y = b;
    return *reinterpret_cast<uint32_t*>(&t);
}
__device__ __forceinline__ uint32_t pack2f(float a, float b) {
    return pack2h(__float2half_rn(a), __float2half_rn(b));
}

// ---------------------------------------------------------------- prep
__global__ void prep_kernel(
    const float* __restrict__ W1, const float* __restrict__ b1,
    const float* __restrict__ W2, const float* __restrict__ b2,
    const float* __restrict__ Wi0, const float* __restrict__ Wi1,
    const float* __restrict__ Wi2)
{
    int idx = blockIdx.x * 256 + threadIdx.x;
    if (idx < N1P * K1P) {
        int n = idx / K1P, k = idx - n * K1P;
        float v = 0.f;
        if (n < HID) {
            if (k < 530)       v = W1[(size_t)k * HID + n];
            else if (k == 530) v = b1[n];
        }
        g_w1t[idx] = __float2half_rn(v);
    }
    if (idx < OUT2 * K2P) {
        int n = idx / K2P, k = idx - n * K2P;
        float v = 0.f;
        if (k < HID)       v = W2[(size_t)k * OUT2 + n];
        else if (k == HID) v = b2[n];
        g_w2t[idx] = __float2half_rn(v);
    }
    if (idx < NIP * KIP) {
        int n = idx / KIP, k = idx - n * KIP;
        float v = 0.f;
        if (n < 8)        v = Wi0[(size_t)k * 8 + n];
        else if (n < 14)  v = Wi1[(size_t)k * 6 + (n - 8)];
        else if (n < 18)  v = Wi2[(size_t)k * 4 + (n - 14)];
        g_wit[idx] = __float2half_rn(v);
    }
}

// stage 64x64 fp32 feature chunk -> fp16 smem (stride 72 halfs)
__device__ __forceinline__ void stage_feat(
    __half* sA, const float* __restrict__ src, int row0, int c0, int tid)
{
    #pragma unroll
    for (int j = 0; j < 4; j++) {
        int i = tid + j * 256;                 // 64*16 = 1024 quads
        int r = i >> 4, ce = (i & 15) << 2;
        float4 v = *(const float4*)(src + (size_t)(row0 + r) * FEAT + c0 + ce);
        uint2 u;
        u.x = pack2f(v.x, v.y);
        u.y = pack2f(v.z, v.w);
        *(uint2*)(sA + r * 72 + ce) = u;
    }
}
__device__ __forceinline__ void stage_b1(__half* sB, int k64, int tid)
{
    #pragma unroll
    for (int j = 0; j < 5; j++) {
        int i = tid + j * 256;                 // 144*8 = 1152 uint4
        if (i < 1152) {
            int n = i >> 3, ce = (i & 7) << 3;
            *(uint4*)(sB + n * 72 + ce) =
                *(const uint4*)(g_w1t + (size_t)n * K1P + k64 + ce);
        }
    }
}
__device__ __forceinline__ void stage_wi(__half* sW, int k64, int tid)
{
    if (tid < 192) {                           // 24*8 uint4
        int n = tid >> 3, ce = (tid & 7) << 3;
        *(uint4*)(sW + n * 72 + ce) =
            *(const uint4*)(g_wit + (size_t)n * KIP + k64 + ce);
    }
}
// special chunk (one-hot + bias-one): thread r owns row r -> race-free
__device__ __forceinline__ void stage_special(
    __half* sA, const int* __restrict__ actions, int row0, int tid)
{
    if (tid < 64) {
        int r = tid;
        #pragma unroll
        for (int q = 0; q < 8; q++)            // cols 0..63 (ldsm reads < 64)
            *(uint4*)(sA + r * 72 + q * 8) = make_uint4(0, 0, 0, 0);
        int f = (row0 + r) >> 5, ag = (row0 + r) & 31;
        int i0 = actions[(f * 3 + 0) * N_AGENTS + ag];
        int i1 = actions[(f * 3 + 1) * N_AGENTS + ag];
        int i2 = actions[(f * 3 + 2) * N_AGENTS + ag];
        __half one = __float2half_rn(1.f);
        sA[r * 72 + i0] = one;
        sA[r * 72 + 8 + i1] = one;
        sA[r * 72 + 14 + i2] = one;
        sA[r * 72 + 18] = one;                 // b1 column (k=530)
    }
}
// stage W2 chunk: 64 n-rows x 144 k (stride 152)
__device__ __forceinline__ void stage_w2(__half* sW2, int c, int tid)
{
    #pragma unroll
    for (int j = 0; j < 5; j++) {
        int i = tid + j * 256;
        if (i < 1152) {
            int n = i / 18, t = i - n * 18;
            *(uint4*)(sW2 + n * 152 + t * 8) =
                *(const uint4*)(g_w2t + (size_t)(c * 64 + n) * K2P + t * 8);
        }
    }
}

// ---------------------------------------------------------------- FUSED 64-row
// 64 rows per CTA, 8 warps, 3 CTAs/SM (85-reg cap).
// phase1: hid = [cur|onehot|1]@W1aug (acc in regs), logits = [cur|nxt]@Wi
//         warp pair (2g,2g+1) shares rows g*16; inv: even warp nt0-1, odd nt2,
//         both reuse the gemm1 A fragment.
// phase2: hid -> smem fp16, logits -> smem, agent softmax (2 frames/CTA).
// phase3: pred = hid(smem) @ W2aug, 4 chunks of 64 cols.
// smem: sA @0 9216 | sB1 @9216 20736 | sWi @29952 3456 | sL @39936 6400
//       phase2/3 alias: sHid @0 19456 | sW2 @19968 19456       total 46336
#define SA0  0
#define SB1O 9216
#define SWIO 29952
#define SL   39936
#define SHID 0
#define SW2O 19968
#define SM_TOTAL 46336

__global__ __launch_bounds__(256, 3) void fused_all(
    const float* __restrict__ cur, const float* __restrict__ nxt,
    const int* __restrict__ actions, float* __restrict__ out)
{
    extern __shared__ char smem[];
    __half* sA  = (__half*)(smem + SA0);
    __half* sB1 = (__half*)(smem + SB1O);
    __half* sWi = (__half*)(smem + SWIO);
    float*  sL  = (float*) (smem + SL);

    const int tid = threadIdx.x, lane = tid & 31, w = tid >> 5;
    const int row0 = blockIdx.x * 64;
    const int m0 = (w >> 1) * 16;              // warp rows (16)
    const int wodd = w & 1;                    // n-half selector
    const int n0 = wodd * 72;

    // ================= phase 1 =================
    float acc1[9][4];
    #pragma unroll
    for (int b = 0; b < 9; b++)
        #pragma unroll
        for (int c = 0; c < 4; c++) acc1[b][c] = 0.f;
    float accI[2][4];
    #pragma unroll
    for (int b = 0; b < 2; b++)
        #pragma unroll
        for (int c = 0; c < 4; c++) accI[b][c] = 0.f;

    for (int kb = 0; kb < 17; kb++) {
        if (kb) __syncthreads();
        const bool g1 = (kb < 8) || (kb == 16);
        const bool iv = (kb < 16);

        // ---- stage
        if (kb < 8)        stage_feat(sA, cur, row0, kb * 64, tid);
        else if (kb < 16)  stage_feat(sA, nxt, row0, (kb - 8) * 64, tid);
        else               stage_special(sA, actions, row0, tid);
        if (kb < 8)        stage_b1(sB1, kb * 64, tid);
        else if (kb == 16) stage_b1(sB1, 512, tid);
        if (iv)            stage_wi(sWi, kb * 64, tid);
        __syncthreads();

        // ---- compute
        const int kmax = (kb == 16) ? 2 : 4;
        for (int ks = 0; ks < kmax; ks++) {
            int k0 = ks * 16;
            uint32_t a[4];
            {
                int r = m0 + (lane & 15);
                int c = k0 + ((lane >> 4) << 3);
                ldsm_x4(a, smaddr(sA + r * 72 + c));
            }
            if (g1) {
                #pragma unroll
                for (int nt = 0; nt < 9; nt++) {
                    uint32_t b[2];
                    int l15 = lane & 15;
                    int nr = n0 + nt * 8 + (l15 & 7);
                    int c = k0 + ((l15 >> 3) << 3);
                    ldsm_x2(b, smaddr(sB1 + nr * 72 + c));
                    mma_f16(acc1[nt], a, b);
                }
            }
            if (iv) {
                int l15 = lane & 15;
                int c = k0 + ((l15 >> 3) << 3);
                if (!wodd) {
                    #pragma unroll
                    for (int nt = 0; nt < 2; nt++) {
                        uint32_t b[2];
                        ldsm_x2(b, smaddr(sWi + (nt * 8 + (l15 & 7)) * 72 + c));
                        mma_f16(accI[nt], a, b);
                    }
                } else {
                    uint32_t b[2];
                    ldsm_x2(b, smaddr(sWi + (16 + (l15 & 7)) * 72 + c));
                    mma_f16(accI[0], a, b);
                }
            }
        }
    }
    __syncthreads();

    // ================= phase 2: hid -> smem, logits -> smem, softmax =========
    __half* sHid = (__half*)(smem + SHID);     // aliases dead sA
    #pragma unroll
    for (int nt = 0; nt < 9; nt++) {
        int col = n0 + nt * 8 + ((lane & 3) << 1);
        int rl = m0 + (lane >> 2);
        #pragma unroll
        for (int h = 0; h < 2; h++) {
            float v0 = acc1[nt][h * 2 + 0];
            float v1 = acc1[nt][h * 2 + 1];
            if (col == 140) v0 = 1.f;          // ones column (b2)
            *(uint32_t*)(sHid + (rl + h * 8) * 152 + col) = pack2f(v0, v1);
        }
    }
    {
        int rl = m0 + (lane >> 2);
        if (!wodd) {
            #pragma unroll
            for (int nt = 0; nt < 2; nt++) {
                int col = nt * 8 + ((lane & 3) << 1);
                sL[rl * 25 + col]           = accI[nt][0];
                sL[rl * 25 + col + 1]       = accI[nt][1];
                sL[(rl + 8) * 25 + col]     = accI[nt][2];
                sL[(rl + 8) * 25 + col + 1] = accI[nt][3];
            }
        } else {
            int col = 16 + ((lane & 3) << 1);
            sL[rl * 25 + col]           = accI[0][0];
            sL[rl * 25 + col + 1]       = accI[0][1];
            sL[(rl + 8) * 25 + col]     = accI[0][2];
            sL[(rl + 8) * 25 + col + 1] = accI[0][3];
        }
    }
    __syncthreads();

    // stage W2 chunk 0 while softmax runs
    stage_w2((__half*)(smem + SW2O), 0, tid);

    // softmax over 32 agents, 2 frames per CTA, per logit column
    if (tid < 36) {
        int f = tid / 18, j = tid - f * 18;
        float vals[32], mx = -1e30f;
        #pragma unroll
        for (int a = 0; a < 32; a++) {
            vals[a] = sL[(f * 32 + a) * 25 + j];
            mx = fmaxf(mx, vals[a]);
        }
        float s = 0.f;
        #pragma unroll
        for (int a = 0; a < 32; a++) { vals[a] = expf(vals[a] - mx); s += vals[a]; }
        float inv = 1.f / s;
        int frame = blockIdx.x * 2 + f;
        if (j < 8) {
            size_t base = OFF_A0 + (size_t)(frame * 32) * 8 + j;
            #pragma unroll
            for (int a = 0; a < 32; a++) out[base + (size_t)a * 8] = vals[a] * inv;
        } else if (j < 14) {
            size_t base = OFF_A1 + (size_t)(frame * 32) * 6 + (j - 8);
            #pragma unroll
            for (int a = 0; a < 32; a++) out[base + (size_t)a * 6] = vals[a] * inv;
        } else {
            size_t base = OFF_A2 + (size_t)(frame * 32) * 4 + (j - 14);
            #pragma unroll
            for (int a = 0; a < 32; a++) out[base + (size_t)a * 4] = vals[a] * inv;
        }
    }
    __syncthreads();

    // ================= phase 3: gemm2 from smem hid =================
    __half* sW2 = (__half*)(smem + SW2O);
    for (int c = 0; c < 4; c++) {
        if (c) {
            __syncthreads();
            stage_w2(sW2, c, tid);
            __syncthreads();
        }

        float acc[4][4];
        #pragma unroll
        for (int b = 0; b < 4; b++)
            #pragma unroll
            for (int q = 0; q < 4; q++) acc[b][q] = 0.f;

        #pragma unroll
        for (int ks = 0; ks < 9; ks++) {
            int k0 = ks * 16;
            uint32_t a[4];
            {
                int r = m0 + (lane & 15);
                int kc = k0 + ((lane >> 4) << 3);
                ldsm_x4(a, smaddr(sHid + r * 152 + kc));
            }
            #pragma unroll
            for (int nt = 0; nt < 4; nt++) {
                uint32_t b[2];
                int l15 = lane & 15;
                int nr = wodd * 32 + nt * 8 + (l15 & 7);
                int kc = k0 + ((l15 >> 3) << 3);
                ldsm_x2(b, smaddr(sW2 + nr * 152 + kc));
                mma_f16(acc[nt], a, b);
            }
        }

        #pragma unroll
        for (int nt = 0; nt < 4; nt++) {
            int col = c * 64 + wodd * 32 + nt * 8 + ((lane & 3) << 1);
            int rb = row0 + m0 + (lane >> 2);
            *(float2*)(out + (size_t)rb * OUT2 + col) =
                make_float2(acc[nt][0], acc[nt][1]);
            *(float2*)(out + (size_t)(rb + 8) * OUT2 + col) =
                make_float2(acc[nt][2], acc[nt][3]);
        }
    }
}

// ----------------------------------------------------------------
extern "C" void kernel_launch(void* const* d_in, const int* in_sizes, int n_in,
                              void* d_out, int out_size)
{
    const float* cur  = (const float*)d_in[0];
    const float* nxt  = (const float*)d_in[1];
    const int*   acts = (const int*)  d_in[2];
    const float* W1   = (const float*)d_in[3];
    const float* b1   = (const float*)d_in[4];
    const float* W2   = (const float*)d_in[5];
    const float* b2   = (const float*)d_in[6];
    const float* Wi0  = (const float*)d_in[7];
    const float* Wi1  = (const float*)d_in[9];
    const float* Wi2  = (const float*)d_in[11];
    float* out = (float*)d_out;

    cudaFuncSetAttribute(fused_all, cudaFuncAttributeMaxDynamicSharedMemorySize, SM_TOTAL);

    prep_kernel<<<(N1P * K1P + 255) / 256, 256>>>(W1, b1, W2, b2, Wi0, Wi1, Wi2);
    fused_all<<<N_ROWS / 64, 256, SM_TOTAL>>>(cur, nxt, acts, out);
}